// round 2
// baseline (speedup 1.0000x reference)
#include <cuda_runtime.h>
#include <cuda_bf16.h>
#include <math.h>

#define NB 4
#define NL 512
#define ND 256
#define NH 128
#define NEGV (-1e30f)

// ---------------- scratch (device globals) ----------------
__device__ float g_WtA[256*256];       // [j][c] c<128: own_W^T, else comp_W^T
__device__ float g_WtG[512*512];       // gate_W^T [j][c]
__device__ float g_WtI[512*768];       // [j][c] c<384: w_ih_f^T else w_ih_b^T
__device__ float g_P[NB*NL*NH];        // exp(2*own)
__device__ float g_Q[NB*NL*NH];        // exp(2*comp)
__device__ float g_C[NB*NL*ND];        // attention context
__device__ float g_inp[NB*NL*2*ND];    // gated GRU input
__device__ float g_xp[2*NB*NL*384];    // GRU input projections [dir][b*L][3H]

__device__ __forceinline__ float frcp(float x) {
    float r; asm("rcp.approx.f32 %0, %1;" : "=f"(r) : "f"(x)); return r;
}
__device__ __forceinline__ float fsig(float x) {
    return frcp(1.0f + __expf(-x));
}
__device__ __forceinline__ float ftanh(float x) {
    return 1.0f - 2.0f * frcp(__expf(2.0f * x) + 1.0f);
}

// ---------------- K0: weight transposes ----------------
__global__ void k_pre(const float* __restrict__ own_W, const float* __restrict__ comp_W,
                      const float* __restrict__ gate_W, const float* __restrict__ w_ih_f,
                      const float* __restrict__ w_ih_b) {
    int idx = blockIdx.x * 256 + threadIdx.x;
    if (idx < 65536) {
        int c = idx & 255, j = idx >> 8;
        g_WtA[idx] = (c < 128) ? own_W[c*256 + j] : comp_W[(c-128)*256 + j];
    } else if (idx < 65536 + 262144) {
        int i2 = idx - 65536;
        int c = i2 & 511, j = i2 >> 9;
        g_WtG[i2] = gate_W[c*512 + j];
    } else {
        int i3 = idx - (65536 + 262144);
        int c = i3 % 768, j = i3 / 768;
        g_WtI[i3] = (c < 384) ? w_ih_f[c*512 + j] : w_ih_b[(c-384)*512 + j];
    }
}

// ---------------- K1: projections -> P = exp(2*own), Q = exp(2*comp) ----------------
__global__ void __launch_bounds__(256) k_proj(const float* __restrict__ v,
                                              const float* __restrict__ own_b,
                                              const float* __restrict__ comp_b) {
    __shared__ float ash[16*256];
    int tid = threadIdx.x;
    int r0 = blockIdx.x * 16;
    {
        const float4* src = (const float4*)(v + r0*256);
        float4* dst = (float4*)ash;
        #pragma unroll
        for (int i = 0; i < 4; ++i) dst[tid + i*256] = src[tid + i*256];
    }
    __syncthreads();
    int rg = tid >> 6, cl = tid & 63;
    float4 acc[4];
    #pragma unroll
    for (int rr = 0; rr < 4; ++rr) acc[rr] = make_float4(0.f,0.f,0.f,0.f);
    const float* a0 = ash + (rg*4)*256;
    #pragma unroll 8
    for (int j = 0; j < 256; ++j) {
        float4 w = ((const float4*)(g_WtA + j*256))[cl];
        #pragma unroll
        for (int rr = 0; rr < 4; ++rr) {
            float a = a0[rr*256 + j];
            acc[rr].x = fmaf(a, w.x, acc[rr].x);
            acc[rr].y = fmaf(a, w.y, acc[rr].y);
            acc[rr].z = fmaf(a, w.z, acc[rr].z);
            acc[rr].w = fmaf(a, w.w, acc[rr].w);
        }
    }
    if (cl < 32) {
        float4 bb = ((const float4*)own_b)[cl];
        #pragma unroll
        for (int rr = 0; rr < 4; ++rr) {
            int row = r0 + rg*4 + rr;
            float4 o;
            o.x = __expf(2.f*(acc[rr].x + bb.x));
            o.y = __expf(2.f*(acc[rr].y + bb.y));
            o.z = __expf(2.f*(acc[rr].z + bb.z));
            o.w = __expf(2.f*(acc[rr].w + bb.w));
            ((float4*)(g_P + row*128))[cl] = o;
        }
    } else {
        float4 bb = ((const float4*)comp_b)[cl - 32];
        #pragma unroll
        for (int rr = 0; rr < 4; ++rr) {
            int row = r0 + rg*4 + rr;
            float4 o;
            o.x = __expf(2.f*(acc[rr].x + bb.x));
            o.y = __expf(2.f*(acc[rr].y + bb.y));
            o.z = __expf(2.f*(acc[rr].z + bb.z));
            o.w = __expf(2.f*(acc[rr].w + bb.w));
            ((float4*)(g_Q + row*128))[cl - 32] = o;
        }
    }
}

// ---------------- K2: fused scores + softmax + context ----------------
// tanh(a+b) = 1 - 2/(P*Q+1), P = e^{2a}, Q = e^{2b}
#define PST 130
#define SST 513
__global__ void __launch_bounds__(256) k_attn(const float* __restrict__ v,
                                              const float* __restrict__ v_attn,
                                              const int* __restrict__ lengths) {
    __shared__ float Psh[8*PST];
    __shared__ float QV[4160];       // Q tile 32x130 / v tile 16x256
    __shared__ float ssh[8*SST];
    __shared__ float vash[128];
    __shared__ float s_sv;

    int tid = threadIdx.x;
    int b  = blockIdx.x >> 6;
    int qt = blockIdx.x & 63;
    int qrow0 = b*NL + qt*8;
    int len = lengths[b];

    for (int i = tid; i < 8*128; i += 256) {
        int q = i >> 7, h = i & 127;
        Psh[q*PST + h] = g_P[(qrow0 + q)*128 + h];
    }
    if (tid < 128) vash[tid] = -2.0f * v_attn[tid];
    if (tid == 0) {
        float s = 0.f;
        for (int h = 0; h < 128; ++h) s += v_attn[h];
        s_sv = s;
    }

    int q = tid & 7, kslot = tid >> 3;   // 32 k slots
    // ---- phase A: scores ----
    for (int kt = 0; kt < 16; ++kt) {
        __syncthreads();
        int kb = kt * 32;
        for (int i = tid; i < 32*128; i += 256) {
            int k = i >> 7, h = i & 127;
            QV[k*PST + h] = g_Q[(b*NL + kb + k)*128 + h];
        }
        __syncthreads();
        float sv = s_sv;
        const float2* Pp = (const float2*)(Psh + q*PST);
        const float2* vp = (const float2*)vash;
        const float2* Qp = (const float2*)(QV + kslot*PST);
        float acc = 0.f;
        #pragma unroll
        for (int hh = 0; hh < 64; ++hh) {
            float2 p  = Pp[hh];
            float2 qq = Qp[hh];
            float2 va = vp[hh];
            acc = fmaf(va.x, frcp(fmaf(p.x, qq.x, 1.0f)), acc);
            acc = fmaf(va.y, frcp(fmaf(p.y, qq.y, 1.0f)), acc);
        }
        int kg = kb + kslot;
        ssh[q*SST + kg] = (kg < len) ? (sv + acc) : NEGV;
    }
    __syncthreads();

    // ---- phase B: softmax over k (8 warps, 1 q each) ----
    int wid = tid >> 5, lane = tid & 31;
    {
        float* srow = ssh + wid*SST;
        float m = -3.4e38f;
        for (int k = lane; k < 512; k += 32) m = fmaxf(m, srow[k]);
        #pragma unroll
        for (int o = 16; o; o >>= 1) m = fmaxf(m, __shfl_xor_sync(0xffffffffu, m, o));
        float s = 0.f;
        for (int k = lane; k < 512; k += 32) { float e = __expf(srow[k] - m); srow[k] = e; s += e; }
        #pragma unroll
        for (int o = 16; o; o >>= 1) s += __shfl_xor_sync(0xffffffffu, s, o);
        float inv = frcp(s);
        for (int k = lane; k < 512; k += 32) srow[k] *= inv;
    }

    // ---- phase C: context C = attn @ v ----
    int dl = tid & 63, qg = tid >> 6;  // qg 0..3, rows qg and qg+4
    float4 acc0 = make_float4(0.f,0.f,0.f,0.f);
    float4 acc1 = make_float4(0.f,0.f,0.f,0.f);
    for (int kt = 0; kt < 32; ++kt) {
        __syncthreads();
        {
            const float4* src = (const float4*)(v + (b*NL + kt*16)*256);
            float4* dst = (float4*)QV;
            #pragma unroll
            for (int i = 0; i < 4; ++i) dst[tid + i*256] = src[tid + i*256];
        }
        __syncthreads();
        #pragma unroll 4
        for (int kk = 0; kk < 16; ++kk) {
            float4 vv = ((const float4*)QV)[kk*64 + dl];
            float a0 = ssh[qg*SST + kt*16 + kk];
            float a1 = ssh[(qg+4)*SST + kt*16 + kk];
            acc0.x = fmaf(a0, vv.x, acc0.x); acc0.y = fmaf(a0, vv.y, acc0.y);
            acc0.z = fmaf(a0, vv.z, acc0.z); acc0.w = fmaf(a0, vv.w, acc0.w);
            acc1.x = fmaf(a1, vv.x, acc1.x); acc1.y = fmaf(a1, vv.y, acc1.y);
            acc1.z = fmaf(a1, vv.z, acc1.z); acc1.w = fmaf(a1, vv.w, acc1.w);
        }
    }
    ((float4*)(g_C + (qrow0 + qg)*256))[dl] = acc0;
    ((float4*)(g_C + (qrow0 + qg + 4)*256))[dl] = acc1;
}

// ---------------- K3: gate ----------------
__global__ void __launch_bounds__(256) k_gate(const float* __restrict__ v,
                                              const float* __restrict__ gate_b) {
    __shared__ float ash[16*512];
    int tid = threadIdx.x;
    int r0 = blockIdx.x * 16;
    for (int i = tid; i < 16*128; i += 256) {
        int r = i >> 7, j4 = i & 127;
        float4 val = (j4 < 64) ? ((const float4*)(v + (r0+r)*256))[j4]
                               : ((const float4*)(g_C + (r0+r)*256))[j4 - 64];
        ((float4*)(ash + r*512))[j4] = val;
    }
    __syncthreads();
    int rg = tid >> 6, cl = tid & 63;
    float4 acc[4][2];
    #pragma unroll
    for (int rr = 0; rr < 4; ++rr) {
        acc[rr][0] = make_float4(0.f,0.f,0.f,0.f);
        acc[rr][1] = make_float4(0.f,0.f,0.f,0.f);
    }
    const float* a0 = ash + (rg*4)*512;
    #pragma unroll 4
    for (int j = 0; j < 512; ++j) {
        const float4* wrow = (const float4*)(g_WtG + j*512);
        float4 w0 = wrow[cl];
        float4 w1 = wrow[cl + 64];
        #pragma unroll
        for (int rr = 0; rr < 4; ++rr) {
            float a = a0[rr*512 + j];
            acc[rr][0].x = fmaf(a, w0.x, acc[rr][0].x);
            acc[rr][0].y = fmaf(a, w0.y, acc[rr][0].y);
            acc[rr][0].z = fmaf(a, w0.z, acc[rr][0].z);
            acc[rr][0].w = fmaf(a, w0.w, acc[rr][0].w);
            acc[rr][1].x = fmaf(a, w1.x, acc[rr][1].x);
            acc[rr][1].y = fmaf(a, w1.y, acc[rr][1].y);
            acc[rr][1].z = fmaf(a, w1.z, acc[rr][1].z);
            acc[rr][1].w = fmaf(a, w1.w, acc[rr][1].w);
        }
    }
    #pragma unroll
    for (int rr = 0; rr < 4; ++rr) {
        int row = r0 + rg*4 + rr;
        #pragma unroll
        for (int cc = 0; cc < 2; ++cc) {
            int ci = cl + 64*cc;
            float4 gb = ((const float4*)gate_b)[ci];
            float4 inpv = ((const float4*)(ash + (rg*4 + rr)*512))[ci];
            float4 z = acc[rr][cc];
            float4 y;
            y.x = inpv.x * fsig(z.x + gb.x);
            y.y = inpv.y * fsig(z.y + gb.y);
            y.z = inpv.z * fsig(z.z + gb.z);
            y.w = inpv.w * fsig(z.w + gb.w);
            ((float4*)(g_inp + row*512))[ci] = y;
        }
    }
}

// ---------------- K4: GRU input projections, both directions ----------------
__global__ void __launch_bounds__(256) k_xp(const float* __restrict__ b_ih_f,
                                            const float* __restrict__ b_ih_b) {
    __shared__ float ash[16*512];
    int tid = threadIdx.x;
    int r0 = blockIdx.x * 16;
    {
        const float4* src = (const float4*)(g_inp + r0*512);
        float4* dst = (float4*)ash;
        #pragma unroll
        for (int i = 0; i < 8; ++i) dst[tid + i*256] = src[tid + i*256];
    }
    __syncthreads();
    int rg = tid >> 6, cl = tid & 63;
    float4 acc[4][3];
    #pragma unroll
    for (int rr = 0; rr < 4; ++rr)
        #pragma unroll
        for (int cc = 0; cc < 3; ++cc) acc[rr][cc] = make_float4(0.f,0.f,0.f,0.f);
    const float* a0 = ash + (rg*4)*512;
    #pragma unroll 2
    for (int j = 0; j < 512; ++j) {
        const float4* wrow = (const float4*)(g_WtI + j*768);
        float4 w0 = wrow[cl];
        float4 w1 = wrow[cl + 64];
        float4 w2 = wrow[cl + 128];
        #pragma unroll
        for (int rr = 0; rr < 4; ++rr) {
            float a = a0[rr*512 + j];
            acc[rr][0].x = fmaf(a, w0.x, acc[rr][0].x);
            acc[rr][0].y = fmaf(a, w0.y, acc[rr][0].y);
            acc[rr][0].z = fmaf(a, w0.z, acc[rr][0].z);
            acc[rr][0].w = fmaf(a, w0.w, acc[rr][0].w);
            acc[rr][1].x = fmaf(a, w1.x, acc[rr][1].x);
            acc[rr][1].y = fmaf(a, w1.y, acc[rr][1].y);
            acc[rr][1].z = fmaf(a, w1.z, acc[rr][1].z);
            acc[rr][1].w = fmaf(a, w1.w, acc[rr][1].w);
            acc[rr][2].x = fmaf(a, w2.x, acc[rr][2].x);
            acc[rr][2].y = fmaf(a, w2.y, acc[rr][2].y);
            acc[rr][2].z = fmaf(a, w2.z, acc[rr][2].z);
            acc[rr][2].w = fmaf(a, w2.w, acc[rr][2].w);
        }
    }
    #pragma unroll
    for (int rr = 0; rr < 4; ++rr) {
        int row = r0 + rg*4 + rr;
        #pragma unroll
        for (int cc = 0; cc < 3; ++cc) {
            int c0 = cc*256 + cl*4;
            int dir = (c0 >= 384) ? 1 : 0;
            int cL = c0 - dir*384;
            const float* bih = dir ? b_ih_b : b_ih_f;
            float4 bb = *(const float4*)(bih + cL);
            float4 o = acc[rr][cc];
            o.x += bb.x; o.y += bb.y; o.z += bb.z; o.w += bb.w;
            *(float4*)(g_xp + dir*(NB*NL*384) + row*384 + cL) = o;
        }
    }
}

// ---------------- K5: bidirectional GRU scan ----------------
__global__ void __launch_bounds__(384, 1) k_gru(const int* __restrict__ lengths,
                                                const float* __restrict__ w_hh_f,
                                                const float* __restrict__ w_hh_b,
                                                const float* __restrict__ b_hh_f,
                                                const float* __restrict__ b_hh_b,
                                                float* __restrict__ out) {
    __shared__ float4 hsh[32];     // h[128]
    __shared__ float hp[384];
    __shared__ float xps[384];

    int dir = blockIdx.x & 1;
    int b   = blockIdx.x >> 1;
    int j   = threadIdx.x;   // 0..383: owns hp row j
    const float* whh = (dir ? w_hh_b : w_hh_f) + j*128;
    float bhh = (dir ? b_hh_b : b_hh_f)[j];

    float4 warr[32];
    #pragma unroll
    for (int k = 0; k < 32; ++k) warr[k] = ((const float4*)whh)[k];

    if (j < 32) hsh[j] = make_float4(0.f,0.f,0.f,0.f);
    __syncthreads();

    const float* xpbase = g_xp + dir*(NB*NL*384) + b*NL*384;
    int len = lengths[b];

    int l0 = dir ? (NL-1) : 0;
    float xp_next = xpbase[l0*384 + j];

    for (int t = 0; t < NL; ++t) {
        int l = dir ? (NL-1-t) : t;
        float xpv = xp_next;
        if (t < NL-1) {
            int ln = dir ? (NL-2-t) : (t+1);
            xp_next = xpbase[ln*384 + j];
        }
        float acc = bhh;
        #pragma unroll
        for (int k = 0; k < 32; ++k) {
            float4 hv = hsh[k];
            float4 wv = warr[k];
            acc = fmaf(wv.x, hv.x, acc);
            acc = fmaf(wv.y, hv.y, acc);
            acc = fmaf(wv.z, hv.z, acc);
            acc = fmaf(wv.w, hv.w, acc);
        }
        hp[j] = acc;
        xps[j] = xpv;
        __syncthreads();
        if (j < 128) {
            float r = fsig(xps[j]       + hp[j]);
            float z = fsig(xps[j + 128] + hp[j + 128]);
            float n = ftanh(xps[j + 256] + r * hp[j + 256]);
            float hold = ((float*)hsh)[j];
            float hnew = (1.0f - z) * n + z * hold;
            bool m = (l < len);
            ((float*)hsh)[j] = m ? hnew : hold;
            out[(b*NL + l)*256 + dir*128 + j] = m ? hnew : 0.0f;
        }
        __syncthreads();
    }
}

extern "C" void kernel_launch(void* const* d_in, const int* in_sizes, int n_in,
                              void* d_out, int out_size) {
    const float* v      = (const float*)d_in[0];
    const int*   lens   = (const int*)d_in[1];
    // d_in[2] = p_mask (unused; derived from lengths)
    const float* own_W  = (const float*)d_in[3];
    const float* own_b  = (const float*)d_in[4];
    const float* comp_W = (const float*)d_in[5];
    const float* comp_b = (const float*)d_in[6];
    const float* v_attn = (const float*)d_in[7];
    const float* gate_W = (const float*)d_in[8];
    const float* gate_b = (const float*)d_in[9];
    const float* w_ih_f = (const float*)d_in[10];
    const float* w_hh_f = (const float*)d_in[11];
    const float* b_ih_f = (const float*)d_in[12];
    const float* b_hh_f = (const float*)d_in[13];
    const float* w_ih_b = (const float*)d_in[14];
    const float* w_hh_b = (const float*)d_in[15];
    const float* b_ih_b = (const float*)d_in[16];
    const float* b_hh_b = (const float*)d_in[17];
    float* out = (float*)d_out;

    k_pre <<<2816, 256>>>(own_W, comp_W, gate_W, w_ih_f, w_ih_b);
    k_proj<<<NB*NL/16, 256>>>(v, own_b, comp_b);
    k_attn<<<NB*(NL/8), 256>>>(v, v_attn, lens);
    k_gate<<<NB*NL/16, 256>>>(v, gate_b);
    k_xp  <<<NB*NL/16, 256>>>(b_ih_f, b_ih_b);
    k_gru <<<2*NB, 384>>>(lens, w_hh_f, w_hh_b, b_hh_f, b_hh_b, out);
}

// round 3
// speedup vs baseline: 1.3648x; 1.3648x over previous
#include <cuda_runtime.h>
#include <cuda_bf16.h>
#include <math.h>

#define NB 4
#define NL 512
#define ND 256
#define NH 128
#define NEGV (-1e30f)

// ---------------- scratch (device globals) ----------------
__device__ float g_WtA[256*256];       // [j][c] c<128: own_W^T, else comp_W^T
__device__ float g_WtG[512*512];       // gate_W^T [j][c]
__device__ float g_WtI[512*768];       // [j][c] c<384: w_ih_f^T else w_ih_b^T
__device__ float g_P[NB*NL*NH];        // exp(2*own)
__device__ float g_Q[NB*NL*NH];        // exp(2*comp)
__device__ float g_C[NB*NL*ND];        // attention context
__device__ float g_inp[NB*NL*2*ND];    // gated GRU input
__device__ float g_xp[2*NB*NL*384];    // GRU input projections [dir][b*L][3H]

__device__ __forceinline__ float frcp(float x) {
    float r; asm("rcp.approx.f32 %0, %1;" : "=f"(r) : "f"(x)); return r;
}
__device__ __forceinline__ float fsig(float x) {
    return frcp(1.0f + __expf(-x));
}
__device__ __forceinline__ float ftanh(float x) {
    return 1.0f - 2.0f * frcp(__expf(2.0f * x) + 1.0f);
}
__device__ __forceinline__ unsigned long long fma2(unsigned long long a,
                                                   unsigned long long b,
                                                   unsigned long long c) {
    unsigned long long d;
    asm("fma.rn.f32x2 %0, %1, %2, %3;" : "=l"(d) : "l"(a), "l"(b), "l"(c));
    return d;
}

// ---------------- K0: weight transposes ----------------
__global__ void k_pre(const float* __restrict__ own_W, const float* __restrict__ comp_W,
                      const float* __restrict__ gate_W, const float* __restrict__ w_ih_f,
                      const float* __restrict__ w_ih_b) {
    int idx = blockIdx.x * 256 + threadIdx.x;
    if (idx < 65536) {
        int c = idx & 255, j = idx >> 8;
        g_WtA[idx] = (c < 128) ? own_W[c*256 + j] : comp_W[(c-128)*256 + j];
    } else if (idx < 65536 + 262144) {
        int i2 = idx - 65536;
        int c = i2 & 511, j = i2 >> 9;
        g_WtG[i2] = gate_W[c*512 + j];
    } else {
        int i3 = idx - (65536 + 262144);
        int c = i3 % 768, j = i3 / 768;
        g_WtI[i3] = (c < 384) ? w_ih_f[c*512 + j] : w_ih_b[(c-384)*512 + j];
    }
}

// ---------------- K1: projections -> P = exp(2*own), Q = exp(2*comp) ----------------
// grid = 128 row-tiles x 2 col-tiles. block: 16 rows x 128 cols.
__global__ void __launch_bounds__(256) k_proj(const float* __restrict__ v,
                                              const float* __restrict__ own_b,
                                              const float* __restrict__ comp_b) {
    __shared__ float ash[16*256];
    int tid = threadIdx.x;
    int rt = blockIdx.x >> 1, ct = blockIdx.x & 1;
    int r0 = rt * 16;
    {
        const float4* src = (const float4*)(v + r0*256);
        float4* dst = (float4*)ash;
        #pragma unroll
        for (int i = 0; i < 4; ++i) dst[tid + i*256] = src[tid + i*256];
    }
    __syncthreads();
    int rg = tid >> 5, cl = tid & 31;   // 8 row-groups x 2 rows, 32 col threads
    float4 acc0 = make_float4(0.f,0.f,0.f,0.f);
    float4 acc1 = make_float4(0.f,0.f,0.f,0.f);
    const float* a0 = ash + (rg*2)*256;
    const float4* wp = (const float4*)g_WtA + ct*32 + cl;
    #pragma unroll 8
    for (int j = 0; j < 256; ++j) {
        float4 w = wp[j*64];
        float x0 = a0[j], x1 = a0[256 + j];
        acc0.x = fmaf(x0, w.x, acc0.x); acc0.y = fmaf(x0, w.y, acc0.y);
        acc0.z = fmaf(x0, w.z, acc0.z); acc0.w = fmaf(x0, w.w, acc0.w);
        acc1.x = fmaf(x1, w.x, acc1.x); acc1.y = fmaf(x1, w.y, acc1.y);
        acc1.z = fmaf(x1, w.z, acc1.z); acc1.w = fmaf(x1, w.w, acc1.w);
    }
    const float* bias = ct ? comp_b : own_b;
    float* outp = ct ? g_Q : g_P;
    float4 bb = ((const float4*)bias)[cl];
    int row = r0 + rg*2;
    float4 o;
    o.x = __expf(2.f*(acc0.x + bb.x)); o.y = __expf(2.f*(acc0.y + bb.y));
    o.z = __expf(2.f*(acc0.z + bb.z)); o.w = __expf(2.f*(acc0.w + bb.w));
    ((float4*)(outp + row*128))[cl] = o;
    o.x = __expf(2.f*(acc1.x + bb.x)); o.y = __expf(2.f*(acc1.y + bb.y));
    o.z = __expf(2.f*(acc1.z + bb.z)); o.w = __expf(2.f*(acc1.w + bb.w));
    ((float4*)(outp + (row+1)*128))[cl] = o;
}

// ---------------- K2: fused scores + softmax + context ----------------
// tanh(a+b) = 1 - 2/(P*Q+1), P = e^{2a}, Q = e^{2b}
#define PST 130
#define SST 513
__global__ void __launch_bounds__(256) k_attn(const float* __restrict__ v,
                                              const float* __restrict__ v_attn,
                                              const int* __restrict__ lengths) {
    __shared__ float Psh[8*PST];
    __shared__ float QV[4160];       // Q tile 32x130 / v tile 16x256
    __shared__ float ssh[8*SST];
    __shared__ float vash[128];
    __shared__ float s_sv;

    int tid = threadIdx.x;
    int b  = blockIdx.x >> 6;
    int qt = blockIdx.x & 63;
    int qrow0 = b*NL + qt*8;
    int len = lengths[b];

    for (int i = tid; i < 8*128; i += 256) {
        int q = i >> 7, h = i & 127;
        Psh[q*PST + h] = g_P[(qrow0 + q)*128 + h];
    }
    if (tid < 128) vash[tid] = -2.0f * v_attn[tid];
    if (tid == 0) {
        float s = 0.f;
        for (int h = 0; h < 128; ++h) s += v_attn[h];
        s_sv = s;
    }

    int q = tid & 7, kslot = tid >> 3;   // 32 k slots
    // ---- phase A: scores ----
    for (int kt = 0; kt < 16; ++kt) {
        int kb = kt * 32;
        if (kb < len) {                   // uniform branch per block
            __syncthreads();
            for (int i = tid; i < 32*128; i += 256) {
                int k = i >> 7, h = i & 127;
                QV[k*PST + h] = g_Q[(b*NL + kb + k)*128 + h];
            }
            __syncthreads();
            float sv = s_sv;
            const float2* Pp = (const float2*)(Psh + q*PST);
            const float2* vp = (const float2*)vash;
            const float2* Qp = (const float2*)(QV + kslot*PST);
            float acc = 0.f;
            #pragma unroll
            for (int hh = 0; hh < 64; ++hh) {
                float2 p  = Pp[hh];
                float2 qq = Qp[hh];
                float2 va = vp[hh];
                acc = fmaf(va.x, frcp(fmaf(p.x, qq.x, 1.0f)), acc);
                acc = fmaf(va.y, frcp(fmaf(p.y, qq.y, 1.0f)), acc);
            }
            int kg = kb + kslot;
            ssh[q*SST + kg] = (kg < len) ? (sv + acc) : NEGV;
        } else {
            ssh[q*SST + kb + kslot] = NEGV;
        }
    }
    __syncthreads();

    // ---- phase B: softmax over k (8 warps, 1 q each) ----
    int wid = tid >> 5, lane = tid & 31;
    {
        float* srow = ssh + wid*SST;
        float m = -3.4e38f;
        for (int k = lane; k < 512; k += 32) m = fmaxf(m, srow[k]);
        #pragma unroll
        for (int o = 16; o; o >>= 1) m = fmaxf(m, __shfl_xor_sync(0xffffffffu, m, o));
        float s = 0.f;
        for (int k = lane; k < 512; k += 32) { float e = __expf(srow[k] - m); srow[k] = e; s += e; }
        #pragma unroll
        for (int o = 16; o; o >>= 1) s += __shfl_xor_sync(0xffffffffu, s, o);
        float inv = frcp(s);
        for (int k = lane; k < 512; k += 32) srow[k] *= inv;
    }

    // ---- phase C: context C = attn @ v ----
    int dl = tid & 63, qg = tid >> 6;  // qg 0..3, rows qg and qg+4
    float4 acc0 = make_float4(0.f,0.f,0.f,0.f);
    float4 acc1 = make_float4(0.f,0.f,0.f,0.f);
    for (int kt = 0; kt < 32; ++kt) {
        int kb = kt * 16;
        if (kb >= len) break;            // uniform: attn is 0 there
        __syncthreads();
        {
            const float4* src = (const float4*)(v + (b*NL + kb)*256);
            float4* dst = (float4*)QV;
            #pragma unroll
            for (int i = 0; i < 4; ++i) dst[tid + i*256] = src[tid + i*256];
        }
        __syncthreads();
        #pragma unroll 4
        for (int kk = 0; kk < 16; ++kk) {
            float4 vv = ((const float4*)QV)[kk*64 + dl];
            float a0 = ssh[qg*SST + kb + kk];
            float a1 = ssh[(qg+4)*SST + kb + kk];
            acc0.x = fmaf(a0, vv.x, acc0.x); acc0.y = fmaf(a0, vv.y, acc0.y);
            acc0.z = fmaf(a0, vv.z, acc0.z); acc0.w = fmaf(a0, vv.w, acc0.w);
            acc1.x = fmaf(a1, vv.x, acc1.x); acc1.y = fmaf(a1, vv.y, acc1.y);
            acc1.z = fmaf(a1, vv.z, acc1.z); acc1.w = fmaf(a1, vv.w, acc1.w);
        }
    }
    ((float4*)(g_C + (qrow0 + qg)*256))[dl] = acc0;
    ((float4*)(g_C + (qrow0 + qg + 4)*256))[dl] = acc1;
}

// ---------------- K3: gate ----------------
// grid = 128 row-tiles x 4 col-tiles. block: 16 rows x 128 cols.
__global__ void __launch_bounds__(256) k_gate(const float* __restrict__ v,
                                              const float* __restrict__ gate_b) {
    __shared__ float ash[16*512];
    int tid = threadIdx.x;
    int rt = blockIdx.x >> 2, ct = blockIdx.x & 3;
    int r0 = rt * 16;
    for (int i = tid; i < 16*128; i += 256) {
        int r = i >> 7, j4 = i & 127;
        float4 val = (j4 < 64) ? ((const float4*)(v + (r0+r)*256))[j4]
                               : ((const float4*)(g_C + (r0+r)*256))[j4 - 64];
        ((float4*)(ash + r*512))[j4] = val;
    }
    __syncthreads();
    int rg = tid >> 5, cl = tid & 31;
    float4 acc0 = make_float4(0.f,0.f,0.f,0.f);
    float4 acc1 = make_float4(0.f,0.f,0.f,0.f);
    const float* a0 = ash + (rg*2)*512;
    const float4* wp = (const float4*)g_WtG + ct*32 + cl;
    #pragma unroll 8
    for (int j = 0; j < 512; ++j) {
        float4 w = wp[j*128];
        float x0 = a0[j], x1 = a0[512 + j];
        acc0.x = fmaf(x0, w.x, acc0.x); acc0.y = fmaf(x0, w.y, acc0.y);
        acc0.z = fmaf(x0, w.z, acc0.z); acc0.w = fmaf(x0, w.w, acc0.w);
        acc1.x = fmaf(x1, w.x, acc1.x); acc1.y = fmaf(x1, w.y, acc1.y);
        acc1.z = fmaf(x1, w.z, acc1.z); acc1.w = fmaf(x1, w.w, acc1.w);
    }
    int ci = ct*32 + cl;
    float4 gb = ((const float4*)gate_b)[ci];
    #pragma unroll
    for (int rr = 0; rr < 2; ++rr) {
        int rl = rg*2 + rr;
        int row = r0 + rl;
        float4 z = rr ? acc1 : acc0;
        float4 inpv = ((const float4*)(ash + rl*512))[ci];
        float4 y;
        y.x = inpv.x * fsig(z.x + gb.x);
        y.y = inpv.y * fsig(z.y + gb.y);
        y.z = inpv.z * fsig(z.z + gb.z);
        y.w = inpv.w * fsig(z.w + gb.w);
        ((float4*)(g_inp + row*512))[ci] = y;
    }
}

// ---------------- K4: GRU input projections, both directions ----------------
// grid = 128 row-tiles x 6 col-tiles. block: 16 rows x 128 cols.
__global__ void __launch_bounds__(256) k_xp(const float* __restrict__ b_ih_f,
                                            const float* __restrict__ b_ih_b) {
    __shared__ float ash[16*512];
    int tid = threadIdx.x;
    int rt = blockIdx.x / 6, ct = blockIdx.x % 6;
    int r0 = rt * 16;
    {
        const float4* src = (const float4*)(g_inp + r0*512);
        float4* dst = (float4*)ash;
        #pragma unroll
        for (int i = 0; i < 8; ++i) dst[tid + i*256] = src[tid + i*256];
    }
    __syncthreads();
    int rg = tid >> 5, cl = tid & 31;
    float4 acc0 = make_float4(0.f,0.f,0.f,0.f);
    float4 acc1 = make_float4(0.f,0.f,0.f,0.f);
    const float* a0 = ash + (rg*2)*512;
    const float4* wp = (const float4*)g_WtI + ct*32 + cl;
    #pragma unroll 8
    for (int j = 0; j < 512; ++j) {
        float4 w = wp[j*192];
        float x0 = a0[j], x1 = a0[512 + j];
        acc0.x = fmaf(x0, w.x, acc0.x); acc0.y = fmaf(x0, w.y, acc0.y);
        acc0.z = fmaf(x0, w.z, acc0.z); acc0.w = fmaf(x0, w.w, acc0.w);
        acc1.x = fmaf(x1, w.x, acc1.x); acc1.y = fmaf(x1, w.y, acc1.y);
        acc1.z = fmaf(x1, w.z, acc1.z); acc1.w = fmaf(x1, w.w, acc1.w);
    }
    int c0 = ct*128 + cl*4;
    int dir = (c0 >= 384) ? 1 : 0;
    int cL = c0 - dir*384;
    const float* bih = dir ? b_ih_b : b_ih_f;
    float4 bb = *(const float4*)(bih + cL);
    int row = r0 + rg*2;
    float4 o;
    o.x = acc0.x + bb.x; o.y = acc0.y + bb.y; o.z = acc0.z + bb.z; o.w = acc0.w + bb.w;
    *(float4*)(g_xp + dir*(NB*NL*384) + row*384 + cL) = o;
    o.x = acc1.x + bb.x; o.y = acc1.y + bb.y; o.z = acc1.z + bb.z; o.w = acc1.w + bb.w;
    *(float4*)(g_xp + dir*(NB*NL*384) + (row+1)*384 + cL) = o;
}

// ---------------- K5: bidirectional GRU scan (f32x2 + early exit) ----------------
__global__ void __launch_bounds__(384, 1) k_gru(const int* __restrict__ lengths,
                                                const float* __restrict__ w_hh_f,
                                                const float* __restrict__ w_hh_b,
                                                const float* __restrict__ b_hh_f,
                                                const float* __restrict__ b_hh_b,
                                                float* __restrict__ out) {
    __shared__ ulonglong2 h2v[32];   // h[128] as f32x2 pairs
    __shared__ float hp[384];

    int dir = blockIdx.x & 1;
    int b   = blockIdx.x >> 1;
    int j   = threadIdx.x;   // 0..383: owns hp row j
    int len = lengths[b];
    const float* whh = (dir ? w_hh_b : w_hh_f) + j*128;
    float bhh = (dir ? b_hh_b : b_hh_f)[j];
    float* hf = (float*)h2v;

    unsigned long long w2[64];
    {
        const ulonglong2* wpk = (const ulonglong2*)whh;
        #pragma unroll
        for (int k = 0; k < 32; ++k) {
            ulonglong2 t = wpk[k];
            w2[2*k] = t.x; w2[2*k+1] = t.y;
        }
    }

    // zero-fill out rows l in [len, NL)
    {
        int n = (NL - len) * 128;
        for (int i = j; i < n; i += 384) {
            int l = len + (i >> 7);
            out[(b*NL + l)*256 + dir*128 + (i & 127)] = 0.0f;
        }
    }

    if (j < 32) h2v[j] = make_ulonglong2(0ull, 0ull);
    __syncthreads();

    const float* xpbase = g_xp + dir*(NB*NL*384) + b*NL*384;

    float xr_c = 0.f, xz_c = 0.f, xn_c = 0.f;
    if (j < 128) {
        int l0 = dir ? (len-1) : 0;
        const float* p = xpbase + l0*384 + j;
        xr_c = p[0]; xz_c = p[128]; xn_c = p[256];
    }

    for (int t = 0; t < len; ++t) {
        int l = dir ? (len-1-t) : t;
        // matvec: hp[j] = bhh + w_hh[j,:] . h
        unsigned long long a0 = 0ull, a1 = 0ull, a2 = 0ull, a3 = 0ull;
        #pragma unroll
        for (int k = 0; k < 32; k += 2) {
            ulonglong2 hA = h2v[k];
            ulonglong2 hB = h2v[k+1];
            a0 = fma2(w2[2*k],   hA.x, a0);
            a1 = fma2(w2[2*k+1], hA.y, a1);
            a2 = fma2(w2[2*k+2], hB.x, a2);
            a3 = fma2(w2[2*k+3], hB.y, a3);
        }
        float s = bhh;
        s += __uint_as_float((unsigned)(a0 & 0xffffffffull)) + __uint_as_float((unsigned)(a0 >> 32));
        s += __uint_as_float((unsigned)(a1 & 0xffffffffull)) + __uint_as_float((unsigned)(a1 >> 32));
        s += __uint_as_float((unsigned)(a2 & 0xffffffffull)) + __uint_as_float((unsigned)(a2 >> 32));
        s += __uint_as_float((unsigned)(a3 & 0xffffffffull)) + __uint_as_float((unsigned)(a3 >> 32));
        hp[j] = s;
        __syncthreads();
        if (j < 128) {
            float r = fsig(xr_c + hp[j]);
            float z = fsig(xz_c + hp[j + 128]);
            float n = ftanh(xn_c + r * hp[j + 256]);
            float hold = hf[j];
            float hnew = (1.0f - z) * n + z * hold;
            hf[j] = hnew;
            out[(b*NL + l)*256 + dir*128 + j] = hnew;
            if (t + 1 < len) {
                int ln = dir ? (len-2-t) : (t+1);
                const float* p = xpbase + ln*384 + j;
                xr_c = p[0]; xz_c = p[128]; xn_c = p[256];
            }
        }
        __syncthreads();
    }
}

extern "C" void kernel_launch(void* const* d_in, const int* in_sizes, int n_in,
                              void* d_out, int out_size) {
    const float* v      = (const float*)d_in[0];
    const int*   lens   = (const int*)d_in[1];
    // d_in[2] = p_mask (unused; derived from lengths)
    const float* own_W  = (const float*)d_in[3];
    const float* own_b  = (const float*)d_in[4];
    const float* comp_W = (const float*)d_in[5];
    const float* comp_b = (const float*)d_in[6];
    const float* v_attn = (const float*)d_in[7];
    const float* gate_W = (const float*)d_in[8];
    const float* gate_b = (const float*)d_in[9];
    const float* w_ih_f = (const float*)d_in[10];
    const float* w_hh_f = (const float*)d_in[11];
    const float* b_ih_f = (const float*)d_in[12];
    const float* b_hh_f = (const float*)d_in[13];
    const float* w_ih_b = (const float*)d_in[14];
    const float* w_hh_b = (const float*)d_in[15];
    const float* b_ih_b = (const float*)d_in[16];
    const float* b_hh_b = (const float*)d_in[17];
    float* out = (float*)d_out;

    k_pre <<<2816, 256>>>(own_W, comp_W, gate_W, w_ih_f, w_ih_b);
    k_proj<<<(NB*NL/16)*2, 256>>>(v, own_b, comp_b);
    k_attn<<<NB*(NL/8), 256>>>(v, v_attn, lens);
    k_gate<<<(NB*NL/16)*4, 256>>>(v, gate_b);
    k_xp  <<<(NB*NL/16)*6, 256>>>(b_ih_f, b_ih_b);
    k_gru <<<2*NB, 384>>>(lens, w_hh_f, w_hh_b, b_hh_f, b_hh_b, out);
}

// round 4
// speedup vs baseline: 1.4079x; 1.0316x over previous
#include <cuda_runtime.h>
#include <cuda_bf16.h>
#include <math.h>

#define NB 4
#define NL 512
#define ND 256
#define NH 128
#define NEGV (-1e30f)

// ---------------- scratch (device globals) ----------------
__device__ float g_WtA[256*256];       // [j][c] c<128: own_W^T, else comp_W^T
__device__ float g_WtG[512*512];       // gate_W^T [j][c]
__device__ float g_WtI[512*768];       // [j][c] c<384: w_ih_f^T else w_ih_b^T
__device__ float g_P[NB*NL*NH];        // exp(2*own)
__device__ float g_Q[NB*NL*NH];        // exp(2*comp)
__device__ float g_C[NB*NL*ND];        // attention context
__device__ float g_inp[NB*NL*2*ND];    // gated GRU input
__device__ float g_xp[2*NB*NL*384];    // GRU input projections [dir][b*L][3H]

__device__ __forceinline__ float frcp(float x) {
    float r; asm("rcp.approx.f32 %0, %1;" : "=f"(r) : "f"(x)); return r;
}
__device__ __forceinline__ float fsig(float x) {
    return frcp(1.0f + __expf(-x));
}
__device__ __forceinline__ float ftanh(float x) {
    return 1.0f - 2.0f * frcp(__expf(2.0f * x) + 1.0f);
}
__device__ __forceinline__ unsigned long long fma2(unsigned long long a,
                                                   unsigned long long b,
                                                   unsigned long long c) {
    unsigned long long d;
    asm("fma.rn.f32x2 %0, %1, %2, %3;" : "=l"(d) : "l"(a), "l"(b), "l"(c));
    return d;
}

// ---------------- K0: weight transposes ----------------
__global__ void k_pre(const float* __restrict__ own_W, const float* __restrict__ comp_W,
                      const float* __restrict__ gate_W, const float* __restrict__ w_ih_f,
                      const float* __restrict__ w_ih_b) {
    int idx = blockIdx.x * 256 + threadIdx.x;
    if (idx < 65536) {
        int c = idx & 255, j = idx >> 8;
        g_WtA[idx] = (c < 128) ? own_W[c*256 + j] : comp_W[(c-128)*256 + j];
    } else if (idx < 65536 + 262144) {
        int i2 = idx - 65536;
        int c = i2 & 511, j = i2 >> 9;
        g_WtG[i2] = gate_W[c*512 + j];
    } else {
        int i3 = idx - (65536 + 262144);
        int c = i3 % 768, j = i3 / 768;
        g_WtI[i3] = (c < 384) ? w_ih_f[c*512 + j] : w_ih_b[(c-384)*512 + j];
    }
}

// ---------------- K1: projections -> P = exp(2*own), Q = exp(2*comp) ----------------
// grid = 128 row-tiles x 2 col-tiles. block: 16 rows x 128 cols.
__global__ void __launch_bounds__(256) k_proj(const float* __restrict__ v,
                                              const float* __restrict__ own_b,
                                              const float* __restrict__ comp_b) {
    __shared__ float ash[16*256];
    int tid = threadIdx.x;
    int rt = blockIdx.x >> 1, ct = blockIdx.x & 1;
    int r0 = rt * 16;
    {
        const float4* src = (const float4*)(v + r0*256);
        float4* dst = (float4*)ash;
        #pragma unroll
        for (int i = 0; i < 4; ++i) dst[tid + i*256] = src[tid + i*256];
    }
    __syncthreads();
    int rg = tid >> 5, cl = tid & 31;   // 8 row-groups x 2 rows, 32 col threads
    float4 acc0 = make_float4(0.f,0.f,0.f,0.f);
    float4 acc1 = make_float4(0.f,0.f,0.f,0.f);
    const float* a0 = ash + (rg*2)*256;
    const float4* wp = (const float4*)g_WtA + ct*32 + cl;
    #pragma unroll 8
    for (int j = 0; j < 256; ++j) {
        float4 w = wp[j*64];
        float x0 = a0[j], x1 = a0[256 + j];
        acc0.x = fmaf(x0, w.x, acc0.x); acc0.y = fmaf(x0, w.y, acc0.y);
        acc0.z = fmaf(x0, w.z, acc0.z); acc0.w = fmaf(x0, w.w, acc0.w);
        acc1.x = fmaf(x1, w.x, acc1.x); acc1.y = fmaf(x1, w.y, acc1.y);
        acc1.z = fmaf(x1, w.z, acc1.z); acc1.w = fmaf(x1, w.w, acc1.w);
    }
    const float* bias = ct ? comp_b : own_b;
    float* outp = ct ? g_Q : g_P;
    float4 bb = ((const float4*)bias)[cl];
    int row = r0 + rg*2;
    float4 o;
    o.x = __expf(2.f*(acc0.x + bb.x)); o.y = __expf(2.f*(acc0.y + bb.y));
    o.z = __expf(2.f*(acc0.z + bb.z)); o.w = __expf(2.f*(acc0.w + bb.w));
    ((float4*)(outp + row*128))[cl] = o;
    o.x = __expf(2.f*(acc1.x + bb.x)); o.y = __expf(2.f*(acc1.y + bb.y));
    o.z = __expf(2.f*(acc1.z + bb.z)); o.w = __expf(2.f*(acc1.w + bb.w));
    ((float4*)(outp + (row+1)*128))[cl] = o;
}

// ---------------- K2: fused scores + softmax + context ----------------
// tanh(a+b) = 1 - 2/(P*Q+1), P = e^{2a}, Q = e^{2b}
#define PST 130
#define SST 513
__global__ void __launch_bounds__(256) k_attn(const float* __restrict__ v,
                                              const float* __restrict__ v_attn,
                                              const int* __restrict__ lengths) {
    __shared__ float Psh[8*PST];
    __shared__ float QV[4160];       // Q tile 32x130 / v tile 16x256
    __shared__ float ssh[8*SST];
    __shared__ float vash[128];
    __shared__ float s_sv;

    int tid = threadIdx.x;
    int b  = blockIdx.x >> 6;
    int qt = blockIdx.x & 63;
    int qrow0 = b*NL + qt*8;
    int len = lengths[b];

    for (int i = tid; i < 8*128; i += 256) {
        int q = i >> 7, h = i & 127;
        Psh[q*PST + h] = g_P[(qrow0 + q)*128 + h];
    }
    if (tid < 128) vash[tid] = -2.0f * v_attn[tid];
    if (tid == 0) {
        float s = 0.f;
        for (int h = 0; h < 128; ++h) s += v_attn[h];
        s_sv = s;
    }

    int q = tid & 7, kslot = tid >> 3;   // 32 k slots
    // ---- phase A: scores ----
    for (int kt = 0; kt < 16; ++kt) {
        int kb = kt * 32;
        if (kb < len) {                   // uniform branch per block
            __syncthreads();
            for (int i = tid; i < 32*128; i += 256) {
                int k = i >> 7, h = i & 127;
                QV[k*PST + h] = g_Q[(b*NL + kb + k)*128 + h];
            }
            __syncthreads();
            float sv = s_sv;
            const float2* Pp = (const float2*)(Psh + q*PST);
            const float2* vp = (const float2*)vash;
            const float2* Qp = (const float2*)(QV + kslot*PST);
            float acc = 0.f;
            #pragma unroll
            for (int hh = 0; hh < 64; ++hh) {
                float2 p  = Pp[hh];
                float2 qq = Qp[hh];
                float2 va = vp[hh];
                acc = fmaf(va.x, frcp(fmaf(p.x, qq.x, 1.0f)), acc);
                acc = fmaf(va.y, frcp(fmaf(p.y, qq.y, 1.0f)), acc);
            }
            int kg = kb + kslot;
            ssh[q*SST + kg] = (kg < len) ? (sv + acc) : NEGV;
        } else {
            ssh[q*SST + kb + kslot] = NEGV;
        }
    }
    __syncthreads();

    // ---- phase B: softmax over k (8 warps, 1 q each) ----
    int wid = tid >> 5, lane = tid & 31;
    {
        float* srow = ssh + wid*SST;
        float m = -3.4e38f;
        for (int k = lane; k < 512; k += 32) m = fmaxf(m, srow[k]);
        #pragma unroll
        for (int o = 16; o; o >>= 1) m = fmaxf(m, __shfl_xor_sync(0xffffffffu, m, o));
        float s = 0.f;
        for (int k = lane; k < 512; k += 32) { float e = __expf(srow[k] - m); srow[k] = e; s += e; }
        #pragma unroll
        for (int o = 16; o; o >>= 1) s += __shfl_xor_sync(0xffffffffu, s, o);
        float inv = frcp(s);
        for (int k = lane; k < 512; k += 32) srow[k] *= inv;
    }

    // ---- phase C: context C = attn @ v ----
    int dl = tid & 63, qg = tid >> 6;  // qg 0..3, rows qg and qg+4
    float4 acc0 = make_float4(0.f,0.f,0.f,0.f);
    float4 acc1 = make_float4(0.f,0.f,0.f,0.f);
    for (int kt = 0; kt < 32; ++kt) {
        int kb = kt * 16;
        if (kb >= len) break;            // uniform: attn is 0 there
        __syncthreads();
        {
            const float4* src = (const float4*)(v + (b*NL + kb)*256);
            float4* dst = (float4*)QV;
            #pragma unroll
            for (int i = 0; i < 4; ++i) dst[tid + i*256] = src[tid + i*256];
        }
        __syncthreads();
        #pragma unroll 4
        for (int kk = 0; kk < 16; ++kk) {
            float4 vv = ((const float4*)QV)[kk*64 + dl];
            float a0 = ssh[qg*SST + kb + kk];
            float a1 = ssh[(qg+4)*SST + kb + kk];
            acc0.x = fmaf(a0, vv.x, acc0.x); acc0.y = fmaf(a0, vv.y, acc0.y);
            acc0.z = fmaf(a0, vv.z, acc0.z); acc0.w = fmaf(a0, vv.w, acc0.w);
            acc1.x = fmaf(a1, vv.x, acc1.x); acc1.y = fmaf(a1, vv.y, acc1.y);
            acc1.z = fmaf(a1, vv.z, acc1.z); acc1.w = fmaf(a1, vv.w, acc1.w);
        }
    }
    ((float4*)(g_C + (qrow0 + qg)*256))[dl] = acc0;
    ((float4*)(g_C + (qrow0 + qg + 4)*256))[dl] = acc1;
}

// ---------------- K3: gate ----------------
// grid = 128 row-tiles x 2 col-tiles. block: 64 cols x 4 groups x 4 rows.
__global__ void __launch_bounds__(256) k_gate(const float* __restrict__ v,
                                              const float* __restrict__ gate_b) {
    __shared__ float ash[16*512];
    int tid = threadIdx.x;
    int rt = blockIdx.x >> 1, ct = blockIdx.x & 1;
    int r0 = rt * 16;
    for (int i = tid; i < 16*128; i += 256) {
        int r = i >> 7, j4 = i & 127;
        float4 val = (j4 < 64) ? ((const float4*)(v + (r0+r)*256))[j4]
                               : ((const float4*)(g_C + (r0+r)*256))[j4 - 64];
        ((float4*)(ash + r*512))[j4] = val;
    }
    __syncthreads();
    int rg = tid >> 6, cl = tid & 63;   // 4 groups x 4 rows, 64 col threads
    float4 acc[4];
    #pragma unroll
    for (int rr = 0; rr < 4; ++rr) acc[rr] = make_float4(0.f,0.f,0.f,0.f);
    const float* a0 = ash + (rg*4)*512;
    const float4* wp = (const float4*)g_WtG + ct*64 + cl;
    #pragma unroll 8
    for (int j = 0; j < 512; ++j) {
        float4 w = wp[j*128];
        #pragma unroll
        for (int rr = 0; rr < 4; ++rr) {
            float x = a0[rr*512 + j];
            acc[rr].x = fmaf(x, w.x, acc[rr].x);
            acc[rr].y = fmaf(x, w.y, acc[rr].y);
            acc[rr].z = fmaf(x, w.z, acc[rr].z);
            acc[rr].w = fmaf(x, w.w, acc[rr].w);
        }
    }
    int ci = ct*64 + cl;
    float4 gb = ((const float4*)gate_b)[ci];
    #pragma unroll
    for (int rr = 0; rr < 4; ++rr) {
        int rl = rg*4 + rr;
        int row = r0 + rl;
        float4 z = acc[rr];
        float4 inpv = ((const float4*)(ash + rl*512))[ci];
        float4 y;
        y.x = inpv.x * fsig(z.x + gb.x);
        y.y = inpv.y * fsig(z.y + gb.y);
        y.z = inpv.z * fsig(z.z + gb.z);
        y.w = inpv.w * fsig(z.w + gb.w);
        ((float4*)(g_inp + row*512))[ci] = y;
    }
}

// ---------------- K4: GRU input projections, both directions ----------------
// grid = 128 row-tiles x 3 col-tiles. block: 64 cols x 4 groups x 4 rows.
__global__ void __launch_bounds__(256) k_xp(const float* __restrict__ b_ih_f,
                                            const float* __restrict__ b_ih_b) {
    __shared__ float ash[16*512];
    int tid = threadIdx.x;
    int rt = blockIdx.x / 3, ct = blockIdx.x % 3;
    int r0 = rt * 16;
    {
        const float4* src = (const float4*)(g_inp + r0*512);
        float4* dst = (float4*)ash;
        #pragma unroll
        for (int i = 0; i < 8; ++i) dst[tid + i*256] = src[tid + i*256];
    }
    __syncthreads();
    int rg = tid >> 6, cl = tid & 63;
    float4 acc[4];
    #pragma unroll
    for (int rr = 0; rr < 4; ++rr) acc[rr] = make_float4(0.f,0.f,0.f,0.f);
    const float* a0 = ash + (rg*4)*512;
    const float4* wp = (const float4*)g_WtI + ct*64 + cl;
    #pragma unroll 8
    for (int j = 0; j < 512; ++j) {
        float4 w = wp[j*192];
        #pragma unroll
        for (int rr = 0; rr < 4; ++rr) {
            float x = a0[rr*512 + j];
            acc[rr].x = fmaf(x, w.x, acc[rr].x);
            acc[rr].y = fmaf(x, w.y, acc[rr].y);
            acc[rr].z = fmaf(x, w.z, acc[rr].z);
            acc[rr].w = fmaf(x, w.w, acc[rr].w);
        }
    }
    int c0 = ct*256 + cl*4;
    int dir = (c0 >= 384) ? 1 : 0;
    int cL = c0 - dir*384;
    const float* bih = dir ? b_ih_b : b_ih_f;
    float4 bb = *(const float4*)(bih + cL);
    #pragma unroll
    for (int rr = 0; rr < 4; ++rr) {
        int row = r0 + rg*4 + rr;
        float4 o = acc[rr];
        o.x += bb.x; o.y += bb.y; o.z += bb.z; o.w += bb.w;
        *(float4*)(g_xp + dir*(NB*NL*384) + row*384 + cL) = o;
    }
}

// ---------------- K5: bidirectional GRU scan (f32x2 + early exit) ----------------
__global__ void __launch_bounds__(384, 1) k_gru(const int* __restrict__ lengths,
                                                const float* __restrict__ w_hh_f,
                                                const float* __restrict__ w_hh_b,
                                                const float* __restrict__ b_hh_f,
                                                const float* __restrict__ b_hh_b,
                                                float* __restrict__ out) {
    __shared__ ulonglong2 h2v[32];   // h[128] as f32x2 pairs
    __shared__ float hp[384];

    int dir = blockIdx.x & 1;
    int b   = blockIdx.x >> 1;
    int j   = threadIdx.x;   // 0..383: owns hp row j
    int len = lengths[b];
    const float* whh = (dir ? w_hh_b : w_hh_f) + j*128;
    float bhh = (dir ? b_hh_b : b_hh_f)[j];
    float* hf = (float*)h2v;

    unsigned long long w2[64];
    {
        const ulonglong2* wpk = (const ulonglong2*)whh;
        #pragma unroll
        for (int k = 0; k < 32; ++k) {
            ulonglong2 t = wpk[k];
            w2[2*k] = t.x; w2[2*k+1] = t.y;
        }
    }

    // zero-fill out rows l in [len, NL)
    {
        int n = (NL - len) * 128;
        for (int i = j; i < n; i += 384) {
            int l = len + (i >> 7);
            out[(b*NL + l)*256 + dir*128 + (i & 127)] = 0.0f;
        }
    }

    if (j < 32) h2v[j] = make_ulonglong2(0ull, 0ull);
    __syncthreads();

    const float* xpbase = g_xp + dir*(NB*NL*384) + b*NL*384;

    float xr_c = 0.f, xz_c = 0.f, xn_c = 0.f;
    if (j < 128) {
        int l0 = dir ? (len-1) : 0;
        const float* p = xpbase + l0*384 + j;
        xr_c = p[0]; xz_c = p[128]; xn_c = p[256];
    }

    for (int t = 0; t < len; ++t) {
        int l = dir ? (len-1-t) : t;
        // matvec: hp[j] = bhh + w_hh[j,:] . h
        unsigned long long a0 = 0ull, a1 = 0ull, a2 = 0ull, a3 = 0ull;
        #pragma unroll
        for (int k = 0; k < 32; k += 2) {
            ulonglong2 hA = h2v[k];
            ulonglong2 hB = h2v[k+1];
            a0 = fma2(w2[2*k],   hA.x, a0);
            a1 = fma2(w2[2*k+1], hA.y, a1);
            a2 = fma2(w2[2*k+2], hB.x, a2);
            a3 = fma2(w2[2*k+3], hB.y, a3);
        }
        float s = bhh;
        s += __uint_as_float((unsigned)(a0 & 0xffffffffull)) + __uint_as_float((unsigned)(a0 >> 32));
        s += __uint_as_float((unsigned)(a1 & 0xffffffffull)) + __uint_as_float((unsigned)(a1 >> 32));
        s += __uint_as_float((unsigned)(a2 & 0xffffffffull)) + __uint_as_float((unsigned)(a2 >> 32));
        s += __uint_as_float((unsigned)(a3 & 0xffffffffull)) + __uint_as_float((unsigned)(a3 >> 32));
        hp[j] = s;
        __syncthreads();
        if (j < 128) {
            float r = fsig(xr_c + hp[j]);
            float z = fsig(xz_c + hp[j + 128]);
            float n = ftanh(xn_c + r * hp[j + 256]);
            float hold = hf[j];
            float hnew = (1.0f - z) * n + z * hold;
            hf[j] = hnew;
            out[(b*NL + l)*256 + dir*128 + j] = hnew;
            if (t + 1 < len) {
                int ln = dir ? (len-2-t) : (t+1);
                const float* p = xpbase + ln*384 + j;
                xr_c = p[0]; xz_c = p[128]; xn_c = p[256];
            }
        }
        __syncthreads();
    }
}

extern "C" void kernel_launch(void* const* d_in, const int* in_sizes, int n_in,
                              void* d_out, int out_size) {
    const float* v      = (const float*)d_in[0];
    const int*   lens   = (const int*)d_in[1];
    // d_in[2] = p_mask (unused; derived from lengths)
    const float* own_W  = (const float*)d_in[3];
    const float* own_b  = (const float*)d_in[4];
    const float* comp_W = (const float*)d_in[5];
    const float* comp_b = (const float*)d_in[6];
    const float* v_attn = (const float*)d_in[7];
    const float* gate_W = (const float*)d_in[8];
    const float* gate_b = (const float*)d_in[9];
    const float* w_ih_f = (const float*)d_in[10];
    const float* w_hh_f = (const float*)d_in[11];
    const float* b_ih_f = (const float*)d_in[12];
    const float* b_hh_f = (const float*)d_in[13];
    const float* w_ih_b = (const float*)d_in[14];
    const float* w_hh_b = (const float*)d_in[15];
    const float* b_ih_b = (const float*)d_in[16];
    const float* b_hh_b = (const float*)d_in[17];
    float* out = (float*)d_out;

    k_pre <<<2816, 256>>>(own_W, comp_W, gate_W, w_ih_f, w_ih_b);
    k_proj<<<(NB*NL/16)*2, 256>>>(v, own_b, comp_b);
    k_attn<<<NB*(NL/8), 256>>>(v, v_attn, lens);
    k_gate<<<(NB*NL/16)*2, 256>>>(v, gate_b);
    k_xp  <<<(NB*NL/16)*3, 256>>>(b_ih_f, b_ih_b);
    k_gru <<<2*NB, 384>>>(lens, w_hh_f, w_hh_b, b_hh_f, b_hh_b, out);
}

// round 5
// speedup vs baseline: 1.5213x; 1.0805x over previous
#include <cuda_runtime.h>
#include <cuda_bf16.h>
#include <math.h>

#define NB 4
#define NL 512
#define ND 256
#define NH 128
#define NEGV (-1e30f)

// ---------------- scratch (device globals) ----------------
__device__ float g_WtA[256*256];       // [j][c] c<128: own_W^T, else comp_W^T
__device__ float g_WtG[512*512];       // gate_W^T [j][c]
__device__ float g_WtI[512*768];       // [j][c] c<384: w_ih_f^T else w_ih_b^T
__device__ float g_bA[256];            // [own_b, comp_b]
__device__ float g_bI[768];            // [b_ih_f, b_ih_b]
__device__ float g_P[NB*NL*NH];        // exp(2*own)
__device__ float g_Q[NB*NL*NH];        // exp(2*comp)
__device__ float g_C[NB*NL*ND];        // attention context
__device__ float g_inp[NB*NL*2*ND];    // gated GRU input
__device__ float g_xp[2*NB*NL*384];    // GRU input projections [dir][b*L][3H]

__device__ __forceinline__ float frcp(float x) {
    float r; asm("rcp.approx.f32 %0, %1;" : "=f"(r) : "f"(x)); return r;
}
__device__ __forceinline__ float fsig(float x) {
    return frcp(1.0f + __expf(-x));
}
__device__ __forceinline__ float ftanh(float x) {
    return 1.0f - 2.0f * frcp(__expf(2.0f * x) + 1.0f);
}
__device__ __forceinline__ unsigned long long fma2(unsigned long long a,
                                                   unsigned long long b,
                                                   unsigned long long c) {
    unsigned long long d;
    asm("fma.rn.f32x2 %0, %1, %2, %3;" : "=l"(d) : "l"(a), "l"(b), "l"(c));
    return d;
}
__device__ __forceinline__ unsigned long long pk2(float lo, float hi) {
    unsigned long long d;
    asm("mov.b64 %0, {%1,%2};" : "=l"(d) : "f"(lo), "f"(hi));
    return d;
}
__device__ __forceinline__ unsigned long long pkdup(float v) {
    unsigned long long d;
    asm("mov.b64 %0, {%1,%1};" : "=l"(d) : "f"(v));
    return d;
}
__device__ __forceinline__ float2 upk(unsigned long long v) {
    float2 r;
    asm("mov.b64 {%0,%1}, %2;" : "=f"(r.x), "=f"(r.y) : "l"(v));
    return r;
}

// ---------------- K0: weight transposes + combined biases ----------------
__global__ void k_pre(const float* __restrict__ own_W, const float* __restrict__ comp_W,
                      const float* __restrict__ gate_W, const float* __restrict__ w_ih_f,
                      const float* __restrict__ w_ih_b, const float* __restrict__ own_b,
                      const float* __restrict__ comp_b, const float* __restrict__ b_ih_f,
                      const float* __restrict__ b_ih_b) {
    int idx = blockIdx.x * 256 + threadIdx.x;
    if (idx < 65536) {
        int c = idx & 255, j = idx >> 8;
        g_WtA[idx] = (c < 128) ? own_W[c*256 + j] : comp_W[(c-128)*256 + j];
    } else if (idx < 65536 + 262144) {
        int i2 = idx - 65536;
        int c = i2 & 511, j = i2 >> 9;
        g_WtG[i2] = gate_W[c*512 + j];
    } else if (idx < 65536 + 262144 + 393216) {
        int i3 = idx - (65536 + 262144);
        int c = i3 % 768, j = i3 / 768;
        g_WtI[i3] = (c < 384) ? w_ih_f[c*512 + j] : w_ih_b[(c-384)*512 + j];
    } else if (idx < 720896 + 256) {
        int c = idx - 720896;
        g_bA[c] = (c < 128) ? own_b[c] : comp_b[c - 128];
    } else if (idx < 720896 + 256 + 768) {
        int c = idx - 720896 - 256;
        g_bI[c] = (c < 384) ? b_ih_f[c] : b_ih_b[c - 384];
    }
}

// ---------------- unified smem-tiled SGEMM (64x64x16 tiles, f32x2 inner) ----------
// EPI: 0 = proj (exp(2*(z+b)) -> g_P/g_Q), 1 = gate (inp*sig(z+b) -> g_inp),
//      2 = xp (z+b -> g_xp per-direction layout)
template<int KDIM, int NDIM, int EPI>
__global__ void __launch_bounds__(256) k_gemm(const float* __restrict__ A,
                                              const float* __restrict__ Aalt,
                                              const float* __restrict__ Wt,
                                              const float* __restrict__ bias) {
    __shared__ float As[64*20];   // [row][k], stride 20
    __shared__ float Bs[16*68];   // [k][n], stride 68
    const int NT = NDIM / 64;
    const int KT = KDIM / 16;
    int tid = threadIdx.x;
    int ntI = blockIdx.x % NT, mtI = blockIdx.x / NT;
    int m0 = mtI * 64, n0 = ntI * 64;

    int arow = tid >> 2, akc = (tid & 3) * 4;   // A: 64 rows x 4 k-groups
    int brow = tid >> 4, bnc = (tid & 15) * 4;  // B: 16 k-rows x 16 n-groups
    const float* Bp = Wt + brow*NDIM + n0 + bnc;

    // first prefetch (kt = 0)
    float4 pa, pb;
    {
        int kg = akc;
        const float* src;
        if (EPI == 1) src = (kg < 256) ? (A + (m0+arow)*256 + kg)
                                       : (Aalt + (m0+arow)*256 + kg - 256);
        else          src = A + (m0+arow)*KDIM + kg;
        pa = *(const float4*)src;
        pb = *(const float4*)Bp;
    }

    int tx = tid & 15, ty = tid >> 4;
    unsigned long long acc[4][2];
    #pragma unroll
    for (int r = 0; r < 4; ++r) { acc[r][0] = 0ull; acc[r][1] = 0ull; }

    for (int kt = 0; kt < KT; ++kt) {
        *(float4*)(As + arow*20 + akc) = pa;
        *(float4*)(Bs + brow*68 + bnc) = pb;
        __syncthreads();
        if (kt + 1 < KT) {
            int kg = (kt+1)*16 + akc;
            const float* src;
            if (EPI == 1) src = (kg < 256) ? (A + (m0+arow)*256 + kg)
                                           : (Aalt + (m0+arow)*256 + kg - 256);
            else          src = A + (m0+arow)*KDIM + kg;
            pa = *(const float4*)src;
            pb = *(const float4*)(Bp + (kt+1)*16*NDIM);
        }
        #pragma unroll
        for (int k = 0; k < 16; ++k) {
            float4 b = *(const float4*)(Bs + k*68 + tx*4);
            unsigned long long b01 = pk2(b.x, b.y);
            unsigned long long b23 = pk2(b.z, b.w);
            #pragma unroll
            for (int r = 0; r < 4; ++r) {
                unsigned long long aa = pkdup(As[(ty*4 + r)*20 + k]);
                acc[r][0] = fma2(aa, b01, acc[r][0]);
                acc[r][1] = fma2(aa, b23, acc[r][1]);
            }
        }
        __syncthreads();
    }

    int cg = n0 + tx*4;
    float4 bb = *(const float4*)(bias + cg);
    #pragma unroll
    for (int r = 0; r < 4; ++r) {
        int row = m0 + ty*4 + r;
        float2 z01 = upk(acc[r][0]);
        float2 z23 = upk(acc[r][1]);
        float4 z = make_float4(z01.x + bb.x, z01.y + bb.y, z23.x + bb.z, z23.y + bb.w);
        if (EPI == 0) {
            float4 y;
            y.x = __expf(2.f*z.x); y.y = __expf(2.f*z.y);
            y.z = __expf(2.f*z.z); y.w = __expf(2.f*z.w);
            float* outp = (cg < 128) ? (g_P + row*128 + cg) : (g_Q + row*128 + cg - 128);
            *(float4*)outp = y;
        } else if (EPI == 1) {
            const float* isrc = (cg < 256) ? (A + row*256 + cg) : (Aalt + row*256 + cg - 256);
            float4 inp = *(const float4*)isrc;
            float4 y;
            y.x = inp.x * fsig(z.x); y.y = inp.y * fsig(z.y);
            y.z = inp.z * fsig(z.z); y.w = inp.w * fsig(z.w);
            *(float4*)(g_inp + row*512 + cg) = y;
        } else {
            int dir = (cg >= 384) ? 1 : 0;
            int cL = cg - dir*384;
            *(float4*)(g_xp + dir*(NB*NL*384) + row*384 + cL) = z;
        }
    }
}

// ---------------- K2: fused scores + softmax + context ----------------
// tanh(a+b) = 1 - 2/(P*Q+1), P = e^{2a}, Q = e^{2b}
#define PST 130
#define SST 513
__global__ void __launch_bounds__(256) k_attn(const float* __restrict__ v,
                                              const float* __restrict__ v_attn,
                                              const int* __restrict__ lengths) {
    __shared__ float Psh[8*PST];
    __shared__ float QV[4160];       // Q tile 32x130 / v tile 16x256
    __shared__ float ssh[8*SST];
    __shared__ float vash[128];
    __shared__ float s_sv;

    int tid = threadIdx.x;
    int b  = blockIdx.x >> 6;
    int qt = blockIdx.x & 63;
    int qrow0 = b*NL + qt*8;
    int len = lengths[b];

    for (int i = tid; i < 8*128; i += 256) {
        int q = i >> 7, h = i & 127;
        Psh[q*PST + h] = g_P[(qrow0 + q)*128 + h];
    }
    if (tid < 128) vash[tid] = -2.0f * v_attn[tid];
    if (tid == 0) {
        float s = 0.f;
        for (int h = 0; h < 128; ++h) s += v_attn[h];
        s_sv = s;
    }

    int q = tid & 7, kslot = tid >> 3;   // 32 k slots
    // ---- phase A: scores ----
    for (int kt = 0; kt < 16; ++kt) {
        int kb = kt * 32;
        if (kb < len) {                   // uniform branch per block
            __syncthreads();
            for (int i = tid; i < 32*128; i += 256) {
                int k = i >> 7, h = i & 127;
                QV[k*PST + h] = g_Q[(b*NL + kb + k)*128 + h];
            }
            __syncthreads();
            float sv = s_sv;
            const float2* Pp = (const float2*)(Psh + q*PST);
            const float2* vp = (const float2*)vash;
            const float2* Qp = (const float2*)(QV + kslot*PST);
            float acc = 0.f;
            #pragma unroll
            for (int hh = 0; hh < 64; ++hh) {
                float2 p  = Pp[hh];
                float2 qq = Qp[hh];
                float2 va = vp[hh];
                acc = fmaf(va.x, frcp(fmaf(p.x, qq.x, 1.0f)), acc);
                acc = fmaf(va.y, frcp(fmaf(p.y, qq.y, 1.0f)), acc);
            }
            int kg = kb + kslot;
            ssh[q*SST + kg] = (kg < len) ? (sv + acc) : NEGV;
        } else {
            ssh[q*SST + kb + kslot] = NEGV;
        }
    }
    __syncthreads();

    // ---- phase B: softmax over k (8 warps, 1 q each) ----
    int wid = tid >> 5, lane = tid & 31;
    {
        float* srow = ssh + wid*SST;
        float m = -3.4e38f;
        for (int k = lane; k < 512; k += 32) m = fmaxf(m, srow[k]);
        #pragma unroll
        for (int o = 16; o; o >>= 1) m = fmaxf(m, __shfl_xor_sync(0xffffffffu, m, o));
        float s = 0.f;
        for (int k = lane; k < 512; k += 32) { float e = __expf(srow[k] - m); srow[k] = e; s += e; }
        #pragma unroll
        for (int o = 16; o; o >>= 1) s += __shfl_xor_sync(0xffffffffu, s, o);
        float inv = frcp(s);
        for (int k = lane; k < 512; k += 32) srow[k] *= inv;
    }

    // ---- phase C: context C = attn @ v ----
    int dl = tid & 63, qg = tid >> 6;  // qg 0..3, rows qg and qg+4
    float4 acc0 = make_float4(0.f,0.f,0.f,0.f);
    float4 acc1 = make_float4(0.f,0.f,0.f,0.f);
    for (int kt = 0; kt < 32; ++kt) {
        int kb = kt * 16;
        if (kb >= len) break;            // uniform: attn is 0 there
        __syncthreads();
        {
            const float4* src = (const float4*)(v + (b*NL + kb)*256);
            float4* dst = (float4*)QV;
            #pragma unroll
            for (int i = 0; i < 4; ++i) dst[tid + i*256] = src[tid + i*256];
        }
        __syncthreads();
        #pragma unroll 4
        for (int kk = 0; kk < 16; ++kk) {
            float4 vv = ((const float4*)QV)[kk*64 + dl];
            float a0 = ssh[qg*SST + kb + kk];
            float a1 = ssh[(qg+4)*SST + kb + kk];
            acc0.x = fmaf(a0, vv.x, acc0.x); acc0.y = fmaf(a0, vv.y, acc0.y);
            acc0.z = fmaf(a0, vv.z, acc0.z); acc0.w = fmaf(a0, vv.w, acc0.w);
            acc1.x = fmaf(a1, vv.x, acc1.x); acc1.y = fmaf(a1, vv.y, acc1.y);
            acc1.z = fmaf(a1, vv.z, acc1.z); acc1.w = fmaf(a1, vv.w, acc1.w);
        }
    }
    ((float4*)(g_C + (qrow0 + qg)*256))[dl] = acc0;
    ((float4*)(g_C + (qrow0 + qg + 4)*256))[dl] = acc1;
}

// ---------------- K5: bidirectional GRU scan (f32x2 + early exit) ----------------
__global__ void __launch_bounds__(384, 1) k_gru(const int* __restrict__ lengths,
                                                const float* __restrict__ w_hh_f,
                                                const float* __restrict__ w_hh_b,
                                                const float* __restrict__ b_hh_f,
                                                const float* __restrict__ b_hh_b,
                                                float* __restrict__ out) {
    __shared__ ulonglong2 h2v[32];   // h[128] as f32x2 pairs
    __shared__ float hp[384];

    int dir = blockIdx.x & 1;
    int b   = blockIdx.x >> 1;
    int j   = threadIdx.x;   // 0..383: owns hp row j
    int len = lengths[b];
    const float* whh = (dir ? w_hh_b : w_hh_f) + j*128;
    float bhh = (dir ? b_hh_b : b_hh_f)[j];
    float* hf = (float*)h2v;

    unsigned long long w2[64];
    {
        const ulonglong2* wpk = (const ulonglong2*)whh;
        #pragma unroll
        for (int k = 0; k < 32; ++k) {
            ulonglong2 t = wpk[k];
            w2[2*k] = t.x; w2[2*k+1] = t.y;
        }
    }

    // zero-fill out rows l in [len, NL)
    {
        int n = (NL - len) * 128;
        for (int i = j; i < n; i += 384) {
            int l = len + (i >> 7);
            out[(b*NL + l)*256 + dir*128 + (i & 127)] = 0.0f;
        }
    }

    if (j < 32) h2v[j] = make_ulonglong2(0ull, 0ull);
    __syncthreads();

    const float* xpbase = g_xp + dir*(NB*NL*384) + b*NL*384;

    float xr_c = 0.f, xz_c = 0.f, xn_c = 0.f;
    if (j < 128) {
        int l0 = dir ? (len-1) : 0;
        const float* p = xpbase + l0*384 + j;
        xr_c = p[0]; xz_c = p[128]; xn_c = p[256];
    }

    for (int t = 0; t < len; ++t) {
        int l = dir ? (len-1-t) : t;
        // matvec: hp[j] = bhh + w_hh[j,:] . h
        unsigned long long a0 = 0ull, a1 = 0ull, a2 = 0ull, a3 = 0ull;
        #pragma unroll
        for (int k = 0; k < 32; k += 2) {
            ulonglong2 hA = h2v[k];
            ulonglong2 hB = h2v[k+1];
            a0 = fma2(w2[2*k],   hA.x, a0);
            a1 = fma2(w2[2*k+1], hA.y, a1);
            a2 = fma2(w2[2*k+2], hB.x, a2);
            a3 = fma2(w2[2*k+3], hB.y, a3);
        }
        float s = bhh;
        s += __uint_as_float((unsigned)(a0 & 0xffffffffull)) + __uint_as_float((unsigned)(a0 >> 32));
        s += __uint_as_float((unsigned)(a1 & 0xffffffffull)) + __uint_as_float((unsigned)(a1 >> 32));
        s += __uint_as_float((unsigned)(a2 & 0xffffffffull)) + __uint_as_float((unsigned)(a2 >> 32));
        s += __uint_as_float((unsigned)(a3 & 0xffffffffull)) + __uint_as_float((unsigned)(a3 >> 32));
        hp[j] = s;
        __syncthreads();
        if (j < 128) {
            float r = fsig(xr_c + hp[j]);
            float z = fsig(xz_c + hp[j + 128]);
            float n = ftanh(xn_c + r * hp[j + 256]);
            float hold = hf[j];
            float hnew = (1.0f - z) * n + z * hold;
            hf[j] = hnew;
            out[(b*NL + l)*256 + dir*128 + j] = hnew;
            if (t + 1 < len) {
                int ln = dir ? (len-2-t) : (t+1);
                const float* p = xpbase + ln*384 + j;
                xr_c = p[0]; xz_c = p[128]; xn_c = p[256];
            }
        }
        __syncthreads();
    }
}

extern "C" void kernel_launch(void* const* d_in, const int* in_sizes, int n_in,
                              void* d_out, int out_size) {
    const float* v      = (const float*)d_in[0];
    const int*   lens   = (const int*)d_in[1];
    // d_in[2] = p_mask (unused; derived from lengths)
    const float* own_W  = (const float*)d_in[3];
    const float* own_b  = (const float*)d_in[4];
    const float* comp_W = (const float*)d_in[5];
    const float* comp_b = (const float*)d_in[6];
    const float* v_attn = (const float*)d_in[7];
    const float* gate_W = (const float*)d_in[8];
    const float* gate_b = (const float*)d_in[9];
    const float* w_ih_f = (const float*)d_in[10];
    const float* w_hh_f = (const float*)d_in[11];
    const float* b_ih_f = (const float*)d_in[12];
    const float* b_hh_f = (const float*)d_in[13];
    const float* w_ih_b = (const float*)d_in[14];
    const float* w_hh_b = (const float*)d_in[15];
    const float* b_ih_b = (const float*)d_in[16];
    const float* b_hh_b = (const float*)d_in[17];
    float* out = (float*)d_out;

    float* d_WtA; cudaGetSymbolAddress((void**)&d_WtA, g_WtA);
    float* d_WtG; cudaGetSymbolAddress((void**)&d_WtG, g_WtG);
    float* d_WtI; cudaGetSymbolAddress((void**)&d_WtI, g_WtI);
    float* d_bA;  cudaGetSymbolAddress((void**)&d_bA,  g_bA);
    float* d_bI;  cudaGetSymbolAddress((void**)&d_bI,  g_bI);
    float* d_C;   cudaGetSymbolAddress((void**)&d_C,   g_C);
    float* d_inp; cudaGetSymbolAddress((void**)&d_inp, g_inp);

    k_pre<<<2821, 256>>>(own_W, comp_W, gate_W, w_ih_f, w_ih_b,
                         own_b, comp_b, b_ih_f, b_ih_b);
    k_gemm<256, 256, 0><<<32*4, 256>>>(v, nullptr, d_WtA, d_bA);
    k_attn<<<NB*(NL/8), 256>>>(v, v_attn, lens);
    k_gemm<512, 512, 1><<<32*8, 256>>>(v, d_C, d_WtG, gate_b);
    k_gemm<512, 768, 2><<<32*12, 256>>>(d_inp, nullptr, d_WtI, d_bI);
    k_gru<<<2*NB, 384>>>(lens, w_hh_f, w_hh_b, b_hh_f, b_hh_b, out);
}

// round 6
// speedup vs baseline: 1.5679x; 1.0306x over previous
#include <cuda_runtime.h>
#include <cuda_bf16.h>
#include <math.h>

#define NB 4
#define NL 512
#define ND 256
#define NH 128
#define NEGV (-1e30f)

// ---------------- scratch (device globals) ----------------
__device__ float g_P[NB*NL*NH];        // exp(2*own)
__device__ float g_Q[NB*NL*NH];        // exp(2*comp)
__device__ float g_C[NB*NL*ND];        // attention context
__device__ float g_inp[NB*NL*2*ND];    // gated GRU input
__device__ float g_xp[2*NB*NL*384];    // GRU input projections [dir][b*L][3H]

__device__ __forceinline__ float frcp(float x) {
    float r; asm("rcp.approx.f32 %0, %1;" : "=f"(r) : "f"(x)); return r;
}
__device__ __forceinline__ float fsig(float x) {
    return frcp(1.0f + __expf(-x));
}
__device__ __forceinline__ float ftanh(float x) {
    return 1.0f - 2.0f * frcp(__expf(2.0f * x) + 1.0f);
}
__device__ __forceinline__ unsigned long long fma2(unsigned long long a,
                                                   unsigned long long b,
                                                   unsigned long long c) {
    unsigned long long d;
    asm("fma.rn.f32x2 %0, %1, %2, %3;" : "=l"(d) : "l"(a), "l"(b), "l"(c));
    return d;
}
__device__ __forceinline__ unsigned long long pkdup(float v) {
    unsigned long long d;
    asm("mov.b64 %0, {%1,%1};" : "=l"(d) : "f"(v));
    return d;
}
__device__ __forceinline__ float2 upk(unsigned long long v) {
    float2 r;
    asm("mov.b64 {%0,%1}, %2;" : "=f"(r.x), "=f"(r.y) : "l"(v));
    return r;
}

// ---------------- unified smem-tiled SGEMM (64x64x16 tiles, f32x2 inner) ----------
// Reads original row-major weights W[n][k] and transposes into smem per tile.
// EPI: 0 = proj (exp(2*(z+b)) -> g_P/g_Q), 1 = gate (inp*sig(z+b) -> g_inp),
//      2 = xp (z+b -> g_xp per-direction layout)
template<int KDIM, int NDIM, int NSPLIT, int EPI>
__global__ void __launch_bounds__(256) k_gemm(const float* __restrict__ A,
                                              const float* __restrict__ Aalt,
                                              const float* __restrict__ W1,
                                              const float* __restrict__ W2,
                                              const float* __restrict__ b1,
                                              const float* __restrict__ b2) {
    __shared__ float As[16*68];   // [k][m], stride 68
    __shared__ float Bs[16*68];   // [k][n], stride 68
    const int NT = NDIM / 64;
    const int KT = KDIM / 16;
    int tid = threadIdx.x;
    int ntI = blockIdx.x % NT, mtI = blockIdx.x / NT;
    int m0 = mtI * 64, n0 = ntI * 64;

    int arow = tid >> 2, akc = (tid & 3) * 4;   // A: 64 rows x 4 k-slots
    int bnr  = tid >> 2, bkc = (tid & 3) * 4;   // B: 64 n-rows x 4 k-slots
    int nr = n0 + bnr;
    const float* wrow = (NSPLIT < NDIM && nr >= NSPLIT) ? (W2 + (nr - NSPLIT)*KDIM)
                                                        : (W1 + nr*KDIM);

    // first prefetch (kt = 0)
    float4 pa, pb;
    {
        int kg = akc;
        const float* src;
        if (EPI == 1) src = (kg < 256) ? (A + (m0+arow)*256 + kg)
                                       : (Aalt + (m0+arow)*256 + kg - 256);
        else          src = A + (m0+arow)*KDIM + kg;
        pa = *(const float4*)src;
        pb = *(const float4*)(wrow + bkc);
    }

    int tx = tid & 15, ty = tid >> 4;
    unsigned long long acc[4][2];
    #pragma unroll
    for (int r = 0; r < 4; ++r) { acc[r][0] = 0ull; acc[r][1] = 0ull; }

    for (int kt = 0; kt < KT; ++kt) {
        As[(akc+0)*68 + arow] = pa.x;
        As[(akc+1)*68 + arow] = pa.y;
        As[(akc+2)*68 + arow] = pa.z;
        As[(akc+3)*68 + arow] = pa.w;
        Bs[(bkc+0)*68 + bnr] = pb.x;
        Bs[(bkc+1)*68 + bnr] = pb.y;
        Bs[(bkc+2)*68 + bnr] = pb.z;
        Bs[(bkc+3)*68 + bnr] = pb.w;
        __syncthreads();
        if (kt + 1 < KT) {
            int kg = (kt+1)*16 + akc;
            const float* src;
            if (EPI == 1) src = (kg < 256) ? (A + (m0+arow)*256 + kg)
                                           : (Aalt + (m0+arow)*256 + kg - 256);
            else          src = A + (m0+arow)*KDIM + kg;
            pa = *(const float4*)src;
            pb = *(const float4*)(wrow + (kt+1)*16 + bkc);
        }
        #pragma unroll
        for (int k = 0; k < 16; ++k) {
            ulonglong2 bp = *(const ulonglong2*)(Bs + k*68 + tx*4);
            float4 av = *(const float4*)(As + k*68 + ty*4);
            unsigned long long a0 = pkdup(av.x);
            unsigned long long a1 = pkdup(av.y);
            unsigned long long a2 = pkdup(av.z);
            unsigned long long a3 = pkdup(av.w);
            acc[0][0] = fma2(a0, bp.x, acc[0][0]); acc[0][1] = fma2(a0, bp.y, acc[0][1]);
            acc[1][0] = fma2(a1, bp.x, acc[1][0]); acc[1][1] = fma2(a1, bp.y, acc[1][1]);
            acc[2][0] = fma2(a2, bp.x, acc[2][0]); acc[2][1] = fma2(a2, bp.y, acc[2][1]);
            acc[3][0] = fma2(a3, bp.x, acc[3][0]); acc[3][1] = fma2(a3, bp.y, acc[3][1]);
        }
        __syncthreads();
    }

    int cg = n0 + tx*4;
    const float* bsrc = (NSPLIT < NDIM && cg >= NSPLIT) ? (b2 + cg - NSPLIT) : (b1 + cg);
    float4 bb = *(const float4*)bsrc;
    #pragma unroll
    for (int r = 0; r < 4; ++r) {
        int row = m0 + ty*4 + r;
        float2 z01 = upk(acc[r][0]);
        float2 z23 = upk(acc[r][1]);
        float4 z = make_float4(z01.x + bb.x, z01.y + bb.y, z23.x + bb.z, z23.y + bb.w);
        if (EPI == 0) {
            float4 y;
            y.x = __expf(2.f*z.x); y.y = __expf(2.f*z.y);
            y.z = __expf(2.f*z.z); y.w = __expf(2.f*z.w);
            float* outp = (cg < 128) ? (g_P + row*128 + cg) : (g_Q + row*128 + cg - 128);
            *(float4*)outp = y;
        } else if (EPI == 1) {
            const float* isrc = (cg < 256) ? (A + row*256 + cg) : (Aalt + row*256 + cg - 256);
            float4 inp = *(const float4*)isrc;
            float4 y;
            y.x = inp.x * fsig(z.x); y.y = inp.y * fsig(z.y);
            y.z = inp.z * fsig(z.z); y.w = inp.w * fsig(z.w);
            *(float4*)(g_inp + row*512 + cg) = y;
        } else {
            int dir = (cg >= 384) ? 1 : 0;
            int cL = cg - dir*384;
            *(float4*)(g_xp + dir*(NB*NL*384) + row*384 + cL) = z;
        }
    }
}

// ---------------- K2: fused scores + softmax + context ----------------
// tanh(a+b) = 1 - 2/(P*Q+1), P = e^{2a}, Q = e^{2b}
#define PST 130
#define SST 513
__global__ void __launch_bounds__(256) k_attn(const float* __restrict__ v,
                                              const float* __restrict__ v_attn,
                                              const int* __restrict__ lengths) {
    __shared__ float Psh[8*PST];
    __shared__ float QV[4160];       // Q tile 32x130 / v tile 16x256
    __shared__ float ssh[8*SST];
    __shared__ float vash[128];
    __shared__ float s_sv;

    int tid = threadIdx.x;
    int b  = blockIdx.x >> 6;
    int qt = blockIdx.x & 63;
    int qrow0 = b*NL + qt*8;
    int len = lengths[b];

    for (int i = tid; i < 8*128; i += 256) {
        int q = i >> 7, h = i & 127;
        Psh[q*PST + h] = g_P[(qrow0 + q)*128 + h];
    }
    if (tid < 128) vash[tid] = -2.0f * v_attn[tid];
    if (tid == 0) {
        float s = 0.f;
        for (int h = 0; h < 128; ++h) s += v_attn[h];
        s_sv = s;
    }

    int q = tid & 7, kslot = tid >> 3;   // 32 k slots
    // ---- phase A: scores ----
    for (int kt = 0; kt < 16; ++kt) {
        int kb = kt * 32;
        if (kb < len) {                   // uniform branch per block
            __syncthreads();
            for (int i = tid; i < 32*128; i += 256) {
                int k = i >> 7, h = i & 127;
                QV[k*PST + h] = g_Q[(b*NL + kb + k)*128 + h];
            }
            __syncthreads();
            float sv = s_sv;
            const float2* Pp = (const float2*)(Psh + q*PST);
            const float2* vp = (const float2*)vash;
            const float2* Qp = (const float2*)(QV + kslot*PST);
            float acc = 0.f;
            #pragma unroll
            for (int hh = 0; hh < 64; ++hh) {
                float2 p  = Pp[hh];
                float2 qq = Qp[hh];
                float2 va = vp[hh];
                acc = fmaf(va.x, frcp(fmaf(p.x, qq.x, 1.0f)), acc);
                acc = fmaf(va.y, frcp(fmaf(p.y, qq.y, 1.0f)), acc);
            }
            int kg = kb + kslot;
            ssh[q*SST + kg] = (kg < len) ? (sv + acc) : NEGV;
        } else {
            ssh[q*SST + kb + kslot] = NEGV;
        }
    }
    __syncthreads();

    // ---- phase B: softmax over k (8 warps, 1 q each) ----
    int wid = tid >> 5, lane = tid & 31;
    {
        float* srow = ssh + wid*SST;
        float m = -3.4e38f;
        for (int k = lane; k < 512; k += 32) m = fmaxf(m, srow[k]);
        #pragma unroll
        for (int o = 16; o; o >>= 1) m = fmaxf(m, __shfl_xor_sync(0xffffffffu, m, o));
        float s = 0.f;
        for (int k = lane; k < 512; k += 32) { float e = __expf(srow[k] - m); srow[k] = e; s += e; }
        #pragma unroll
        for (int o = 16; o; o >>= 1) s += __shfl_xor_sync(0xffffffffu, s, o);
        float inv = frcp(s);
        for (int k = lane; k < 512; k += 32) srow[k] *= inv;
    }

    // ---- phase C: context C = attn @ v ----
    int dl = tid & 63, qg = tid >> 6;  // qg 0..3, rows qg and qg+4
    float4 acc0 = make_float4(0.f,0.f,0.f,0.f);
    float4 acc1 = make_float4(0.f,0.f,0.f,0.f);
    for (int kt = 0; kt < 32; ++kt) {
        int kb = kt * 16;
        if (kb >= len) break;            // uniform: attn is 0 there
        __syncthreads();
        {
            const float4* src = (const float4*)(v + (b*NL + kb)*256);
            float4* dst = (float4*)QV;
            #pragma unroll
            for (int i = 0; i < 4; ++i) dst[tid + i*256] = src[tid + i*256];
        }
        __syncthreads();
        #pragma unroll 4
        for (int kk = 0; kk < 16; ++kk) {
            float4 vv = ((const float4*)QV)[kk*64 + dl];
            float a0 = ssh[qg*SST + kb + kk];
            float a1 = ssh[(qg+4)*SST + kb + kk];
            acc0.x = fmaf(a0, vv.x, acc0.x); acc0.y = fmaf(a0, vv.y, acc0.y);
            acc0.z = fmaf(a0, vv.z, acc0.z); acc0.w = fmaf(a0, vv.w, acc0.w);
            acc1.x = fmaf(a1, vv.x, acc1.x); acc1.y = fmaf(a1, vv.y, acc1.y);
            acc1.z = fmaf(a1, vv.z, acc1.z); acc1.w = fmaf(a1, vv.w, acc1.w);
        }
    }
    ((float4*)(g_C + (qrow0 + qg)*256))[dl] = acc0;
    ((float4*)(g_C + (qrow0 + qg + 4)*256))[dl] = acc1;
}

// ---------------- K5: bidirectional GRU scan (f32x2 + early exit) ----------------
__global__ void __launch_bounds__(384, 1) k_gru(const int* __restrict__ lengths,
                                                const float* __restrict__ w_hh_f,
                                                const float* __restrict__ w_hh_b,
                                                const float* __restrict__ b_hh_f,
                                                const float* __restrict__ b_hh_b,
                                                float* __restrict__ out) {
    __shared__ ulonglong2 h2v[32];   // h[128] as f32x2 pairs
    __shared__ float hp[384];

    int dir = blockIdx.x & 1;
    int b   = blockIdx.x >> 1;
    int j   = threadIdx.x;   // 0..383: owns hp row j
    int len = lengths[b];
    const float* whh = (dir ? w_hh_b : w_hh_f) + j*128;
    float bhh = (dir ? b_hh_b : b_hh_f)[j];
    float* hf = (float*)h2v;

    unsigned long long w2[64];
    {
        const ulonglong2* wpk = (const ulonglong2*)whh;
        #pragma unroll
        for (int k = 0; k < 32; ++k) {
            ulonglong2 t = wpk[k];
            w2[2*k] = t.x; w2[2*k+1] = t.y;
        }
    }

    // zero-fill out rows l in [len, NL)
    {
        int n = (NL - len) * 128;
        for (int i = j; i < n; i += 384) {
            int l = len + (i >> 7);
            out[(b*NL + l)*256 + dir*128 + (i & 127)] = 0.0f;
        }
    }

    if (j < 32) h2v[j] = make_ulonglong2(0ull, 0ull);
    __syncthreads();

    const float* xpbase = g_xp + dir*(NB*NL*384) + b*NL*384;

    float xr_c = 0.f, xz_c = 0.f, xn_c = 0.f;
    if (j < 128) {
        int l0 = dir ? (len-1) : 0;
        const float* p = xpbase + l0*384 + j;
        xr_c = p[0]; xz_c = p[128]; xn_c = p[256];
    }

    for (int t = 0; t < len; ++t) {
        int l = dir ? (len-1-t) : t;
        // matvec: hp[j] = bhh + w_hh[j,:] . h
        unsigned long long a0 = 0ull, a1 = 0ull, a2 = 0ull, a3 = 0ull;
        #pragma unroll
        for (int k = 0; k < 32; k += 2) {
            ulonglong2 hA = h2v[k];
            ulonglong2 hB = h2v[k+1];
            a0 = fma2(w2[2*k],   hA.x, a0);
            a1 = fma2(w2[2*k+1], hA.y, a1);
            a2 = fma2(w2[2*k+2], hB.x, a2);
            a3 = fma2(w2[2*k+3], hB.y, a3);
        }
        float s = bhh;
        s += __uint_as_float((unsigned)(a0 & 0xffffffffull)) + __uint_as_float((unsigned)(a0 >> 32));
        s += __uint_as_float((unsigned)(a1 & 0xffffffffull)) + __uint_as_float((unsigned)(a1 >> 32));
        s += __uint_as_float((unsigned)(a2 & 0xffffffffull)) + __uint_as_float((unsigned)(a2 >> 32));
        s += __uint_as_float((unsigned)(a3 & 0xffffffffull)) + __uint_as_float((unsigned)(a3 >> 32));
        hp[j] = s;
        __syncthreads();
        if (j < 128) {
            float r = fsig(xr_c + hp[j]);
            float z = fsig(xz_c + hp[j + 128]);
            float n = ftanh(xn_c + r * hp[j + 256]);
            float hold = hf[j];
            float hnew = (1.0f - z) * n + z * hold;
            hf[j] = hnew;
            out[(b*NL + l)*256 + dir*128 + j] = hnew;
            if (t + 1 < len) {
                int ln = dir ? (len-2-t) : (t+1);
                const float* p = xpbase + ln*384 + j;
                xr_c = p[0]; xz_c = p[128]; xn_c = p[256];
            }
        }
        __syncthreads();
    }
}

extern "C" void kernel_launch(void* const* d_in, const int* in_sizes, int n_in,
                              void* d_out, int out_size) {
    const float* v      = (const float*)d_in[0];
    const int*   lens   = (const int*)d_in[1];
    // d_in[2] = p_mask (unused; derived from lengths)
    const float* own_W  = (const float*)d_in[3];
    const float* own_b  = (const float*)d_in[4];
    const float* comp_W = (const float*)d_in[5];
    const float* comp_b = (const float*)d_in[6];
    const float* v_attn = (const float*)d_in[7];
    const float* gate_W = (const float*)d_in[8];
    const float* gate_b = (const float*)d_in[9];
    const float* w_ih_f = (const float*)d_in[10];
    const float* w_hh_f = (const float*)d_in[11];
    const float* b_ih_f = (const float*)d_in[12];
    const float* b_hh_f = (const float*)d_in[13];
    const float* w_ih_b = (const float*)d_in[14];
    const float* w_hh_b = (const float*)d_in[15];
    const float* b_ih_b = (const float*)d_in[16];
    const float* b_hh_b = (const float*)d_in[17];
    float* out = (float*)d_out;

    float* d_C;   cudaGetSymbolAddress((void**)&d_C,   g_C);
    float* d_inp; cudaGetSymbolAddress((void**)&d_inp, g_inp);

    k_gemm<256, 256, 128, 0><<<32*4, 256>>>(v, nullptr, own_W, comp_W, own_b, comp_b);
    k_attn<<<NB*(NL/8), 256>>>(v, v_attn, lens);
    k_gemm<512, 512, 512, 1><<<32*8, 256>>>(v, d_C, gate_W, gate_W, gate_b, gate_b);
    k_gemm<512, 768, 384, 2><<<32*12, 256>>>(d_inp, nullptr, w_ih_f, w_ih_b, b_ih_f, b_ih_b);
    k_gru<<<2*NB, 384>>>(lens, w_hh_f, w_hh_b, b_hh_f, b_hh_b, out);
}